// round 6
// baseline (speedup 1.0000x reference)
#include <cuda_runtime.h>
#include <cuda_fp16.h>
#include <cstdint>

// Problem constants (fixed by the reference)
#define N_SRC   100000
#define N_DST   100000
#define N_EDGES 3200000
#define OUT_DIM 64

#define SCAN_BLK 256
#define NUM_BLKS ((N_DST + SCAN_BLK - 1) / SCAN_BLK)   // 391

// Sorted-src capacity: per-row 16B alignment pads <=3 per dst, plus chunk
// over-read margin. Zero-initialized; pad slots are never written -> always 0
// (a valid row-0 offset), masked off by the count guard in accumulate.
#define SORTED_CAP (N_EDGES + 4 * N_DST + 128)

// ---------------------------------------------------------------------------
// Static device scratch (allocation-free per harness rules)
// ---------------------------------------------------------------------------
__device__ __half2 g_feat_h[(size_t)N_SRC * OUT_DIM / 2];  // 12.8 MB fp16 feat
__device__ int     g_counts[N_DST];                        // raw per-dst degrees
__device__ int     g_offsets[N_DST + 1];                   // 4-aligned CSR offsets
__device__ int     g_cursor[N_DST];                        // scatter cursors
__device__ int     g_sorted_src[SORTED_CAP];               // (src<<5) by dst bucket
__device__ int     g_block_sums[512];                      // per-block partial sums

// ---------------------------------------------------------------------------
// Kernel 1: feat_h = (half)(weight[node_ids] * cj). 8 threads/row, 16B each.
// ---------------------------------------------------------------------------
__global__ void prep_feat_kernel(const int* __restrict__ node_ids,
                                 const float* __restrict__ cj,
                                 const float* __restrict__ weight) {
    int t = blockIdx.x * blockDim.x + threadIdx.x;
    if (t >= N_SRC * 8) return;
    int i = t >> 3;          // row
    int c = t & 7;           // 8-half (16B) chunk within row
    int nid = node_ids[i];
    float s = cj[i];
    const float4* wrow = reinterpret_cast<const float4*>(weight + (size_t)nid * OUT_DIM);
    float4 a = wrow[c * 2 + 0];
    float4 b = wrow[c * 2 + 1];
    __half2 h[4];
    h[0] = __floats2half2_rn(a.x * s, a.y * s);
    h[1] = __floats2half2_rn(a.z * s, a.w * s);
    h[2] = __floats2half2_rn(b.x * s, b.y * s);
    h[3] = __floats2half2_rn(b.z * s, b.w * s);
    float4 packed = *reinterpret_cast<const float4*>(h);
    reinterpret_cast<float4*>(g_feat_h)[(size_t)i * 8 + c] = packed;
}

// ---------------------------------------------------------------------------
// Kernel 2: zero histogram counters
// ---------------------------------------------------------------------------
__global__ void zero_counts_kernel() {
    int t = blockIdx.x * blockDim.x + threadIdx.x;
    if (t < N_DST) g_counts[t] = 0;
}

// ---------------------------------------------------------------------------
// Kernel 3: histogram of dst degrees
// ---------------------------------------------------------------------------
__global__ void hist_kernel(const int* __restrict__ dst_idx) {
    int t = blockIdx.x * blockDim.x + threadIdx.x;
    if (t < N_EDGES) atomicAdd(&g_counts[dst_idx[t]], 1);
}

// ---------------------------------------------------------------------------
// Kernel 4a: per-block partial sums of 4-ALIGNED counts (391 blocks x 256)
// ---------------------------------------------------------------------------
__global__ void partial_sums_kernel() {
    __shared__ int ws[8];
    int b = blockIdx.x;
    int i = b * SCAN_BLK + threadIdx.x;
    int v = (i < N_DST) ? ((g_counts[i] + 3) & ~3) : 0;
    #pragma unroll
    for (int off = 16; off; off >>= 1) v += __shfl_down_sync(0xffffffffu, v, off);
    if ((threadIdx.x & 31) == 0) ws[threadIdx.x >> 5] = v;
    __syncthreads();
    if (threadIdx.x < 8) {
        int s = ws[threadIdx.x];
        #pragma unroll
        for (int off = 4; off; off >>= 1) s += __shfl_down_sync(0xffu, s, off);
        if (threadIdx.x == 0) g_block_sums[b] = s;
    }
}

// ---------------------------------------------------------------------------
// Kernel 4b: exclusive scan of the 391 block sums (single block of 512)
// ---------------------------------------------------------------------------
__global__ void scan_sums_kernel() {
    __shared__ int sh[512];
    int tid = threadIdx.x;
    int v = (tid < NUM_BLKS) ? g_block_sums[tid] : 0;
    sh[tid] = v;
    __syncthreads();
    #pragma unroll
    for (int off = 1; off < 512; off <<= 1) {
        int y = (tid >= off) ? sh[tid - off] : 0;
        __syncthreads();
        sh[tid] += y;
        __syncthreads();
    }
    if (tid < NUM_BLKS) g_block_sums[tid] = sh[tid] - v;   // exclusive prefix
    if (tid == 0) g_offsets[N_DST] = sh[511];               // aligned grand total
}

// ---------------------------------------------------------------------------
// Kernel 4c: per-element exclusive offsets (aligned counts) + cursors
// ---------------------------------------------------------------------------
__global__ void offsets_kernel() {
    __shared__ int ws[8];
    int b = blockIdx.x;
    int i = b * SCAN_BLK + threadIdx.x;
    int lane = threadIdx.x & 31;
    int w = threadIdx.x >> 5;

    int v = (i < N_DST) ? ((g_counts[i] + 3) & ~3) : 0;
    int x = v;
    #pragma unroll
    for (int off = 1; off < 32; off <<= 1) {
        int y = __shfl_up_sync(0xffffffffu, x, off);
        if (lane >= off) x += y;
    }
    if (lane == 31) ws[w] = x;
    __syncthreads();
    if (w == 0) {
        int s = (lane < 8) ? ws[lane] : 0;
        #pragma unroll
        for (int off = 1; off < 8; off <<= 1) {
            int y = __shfl_up_sync(0xffffffffu, s, off);
            if (lane >= off) s += y;
        }
        if (lane < 8) ws[lane] = s;
    }
    __syncthreads();
    int excl = (x - v) + (w > 0 ? ws[w - 1] : 0) + g_block_sums[b];
    if (i < N_DST) {
        g_offsets[i] = excl;
        g_cursor[i]  = excl;
    }
}

// ---------------------------------------------------------------------------
// Kernel 5: permute (src<<5) into dst buckets (pre-scaled half2-row offsets)
// ---------------------------------------------------------------------------
__global__ void permute_kernel(const int* __restrict__ src_idx,
                               const int* __restrict__ dst_idx) {
    int t = blockIdx.x * blockDim.x + threadIdx.x;
    if (t >= N_EDGES) return;
    int d = dst_idx[t];
    int pos = atomicAdd(&g_cursor[d], 1);
    g_sorted_src[pos] = src_idx[t] << 5;   // row offset in half2 units
}

// ---------------------------------------------------------------------------
// Kernel 6: warp-per-dst accumulate. Each lane owns one half2 column (4B);
// every edge's 128B row read is one coalesced warp LDG. Indices are loaded as
// int4 per lane (one LDG covers 128 edges warp-wide) and distributed via
// shuffles -> all feature loads in a chunk are independent (MLP ~32/warp).
// fp32 accumulation; ci folded into the single float2 store per lane.
// ---------------------------------------------------------------------------
__global__ void accumulate_kernel(const float* __restrict__ ci,
                                  float* __restrict__ out) {
    int warp = (blockIdx.x * blockDim.x + threadIdx.x) >> 5;
    int lane = threadIdx.x & 31;
    if (warp >= N_DST) return;
    int d = warp;

    int beg = g_offsets[d];
    int cnt = g_counts[d];
    int end = beg + cnt;

    const __half2* __restrict__ feat = g_feat_h;
    float accx = 0.f, accy = 0.f;

    for (int base = beg; base < end; base += 128) {
        // lane loads 4 consecutive indices (16B-aligned by construction)
        int4 idx = *reinterpret_cast<const int4*>(&g_sorted_src[base + lane * 4]);
        int lim = end - base;              // valid edges in this chunk (<=128)
        if (lim > 128) lim = 128;
        int ngroups = (lim + 3) >> 2;

        for (int g = 0; g < ngroups; g++) {
            int s0 = __shfl_sync(0xffffffffu, idx.x, g);
            int s1 = __shfl_sync(0xffffffffu, idx.y, g);
            int s2 = __shfl_sync(0xffffffffu, idx.z, g);
            int s3 = __shfl_sync(0xffffffffu, idx.w, g);
            int rem = lim - (g << 2);      // >=1 here
            if (rem >= 4) {
                __half2 h0 = feat[(size_t)(s0 + lane)];
                __half2 h1 = feat[(size_t)(s1 + lane)];
                __half2 h2 = feat[(size_t)(s2 + lane)];
                __half2 h3 = feat[(size_t)(s3 + lane)];
                float2 f0 = __half22float2(h0);
                float2 f1 = __half22float2(h1);
                float2 f2 = __half22float2(h2);
                float2 f3 = __half22float2(h3);
                accx += f0.x + f1.x + f2.x + f3.x;
                accy += f0.y + f1.y + f2.y + f3.y;
            } else {
                {
                    float2 f = __half22float2(feat[(size_t)(s0 + lane)]);
                    accx += f.x; accy += f.y;
                }
                if (rem > 1) {
                    float2 f = __half22float2(feat[(size_t)(s1 + lane)]);
                    accx += f.x; accy += f.y;
                }
                if (rem > 2) {
                    float2 f = __half22float2(feat[(size_t)(s2 + lane)]);
                    accx += f.x; accy += f.y;
                }
            }
        }
    }

    float sc = ci[d];
    float2 o = make_float2(accx * sc, accy * sc);
    reinterpret_cast<float2*>(out + (size_t)d * OUT_DIM)[lane] = o;
}

// ---------------------------------------------------------------------------
// Launch. Input order per metadata: node_ids, src_idx, dst_idx, cj, ci, weight
// ---------------------------------------------------------------------------
extern "C" void kernel_launch(void* const* d_in, const int* in_sizes, int n_in,
                              void* d_out, int out_size) {
    const int*   node_ids = (const int*)  d_in[0];
    const int*   src_idx  = (const int*)  d_in[1];
    const int*   dst_idx  = (const int*)  d_in[2];
    const float* cj       = (const float*)d_in[3];
    const float* ci       = (const float*)d_in[4];
    const float* weight   = (const float*)d_in[5];
    float*       out      = (float*)      d_out;

    const int THREADS = 256;

    // 1) feat_h = (half)(weight[node_ids] * cj)
    {
        int n = N_SRC * 8;
        prep_feat_kernel<<<(n + THREADS - 1) / THREADS, THREADS>>>(node_ids, cj, weight);
    }
    // 2) zero counters
    zero_counts_kernel<<<(N_DST + THREADS - 1) / THREADS, THREADS>>>();
    // 3) histogram
    hist_kernel<<<(N_EDGES + THREADS - 1) / THREADS, THREADS>>>(dst_idx);
    // 4) three-phase exclusive scan over 4-aligned counts
    partial_sums_kernel<<<NUM_BLKS, SCAN_BLK>>>();
    scan_sums_kernel<<<1, 512>>>();
    offsets_kernel<<<NUM_BLKS, SCAN_BLK>>>();
    // 5) permute (src<<5) by dst bucket
    permute_kernel<<<(N_EDGES + THREADS - 1) / THREADS, THREADS>>>(src_idx, dst_idx);
    // 6) warp-per-dst accumulate + ci scale + store
    {
        int nthreads = N_DST * 32;
        accumulate_kernel<<<(nthreads + THREADS - 1) / THREADS, THREADS>>>(ci, out);
    }
}